// round 1
// baseline (speedup 1.0000x reference)
#include <cuda_runtime.h>
#include <math.h>

#define B_ 2
#define T_ 2048
#define DM 1024
#define NH 16
#define DK 64

// Scratch (device globals; no allocation allowed)
__device__ float g_QV[B_*T_*DM];   // x@Wq.T+bq  (pre-RoPE) == V
__device__ float g_Kp[B_*T_*DM];   // x@Wk.T+bk  (pre-RoPE)
__device__ float g_Qr[B_*T_*DM];   // RoPE(Q)
__device__ float g_Kr[B_*T_*DM];   // RoPE(K)
__device__ float g_At[B_*T_*DM];   // attention heads output [b,t,h*64+d]

// ---------------------------------------------------------------------------
// SGEMM: C[m,n] = sum_k A[m,k] * W[n,k] + bias[n]   (A row-major, W row-major)
// BM=BN=128, BK=8, 256 threads, 8x8 per thread
// ---------------------------------------------------------------------------
#define BM 128
#define BN 128
#define BKK 8
#define TM 8
#define TN 8

__global__ __launch_bounds__(256, 2)
void sgemm_nt_bias(float* __restrict__ C, const float* __restrict__ A,
                   const float* __restrict__ W, const float* __restrict__ bias,
                   int M, int N, int K)
{
    __shared__ float As[BKK][BM];
    __shared__ float Bs[BKK][BN];

    const int tid = threadIdx.x;
    const int bm = blockIdx.y * BM;
    const int bn = blockIdx.x * BN;

    const int l_row = tid >> 1;          // 0..127
    const int l_c4  = (tid & 1) * 4;     // 0 or 4

    const int ty = tid >> 4;             // 0..15
    const int tx = tid & 15;             // 0..15

    float acc[TM][TN];
    #pragma unroll
    for (int i = 0; i < TM; i++)
        #pragma unroll
        for (int j = 0; j < TN; j++) acc[i][j] = 0.f;

    for (int k0 = 0; k0 < K; k0 += BKK) {
        const float4 av = *(const float4*)&A[(size_t)(bm + l_row) * K + k0 + l_c4];
        const float4 wv = *(const float4*)&W[(size_t)(bn + l_row) * K + k0 + l_c4];
        __syncthreads();
        As[l_c4 + 0][l_row] = av.x;
        As[l_c4 + 1][l_row] = av.y;
        As[l_c4 + 2][l_row] = av.z;
        As[l_c4 + 3][l_row] = av.w;
        Bs[l_c4 + 0][l_row] = wv.x;
        Bs[l_c4 + 1][l_row] = wv.y;
        Bs[l_c4 + 2][l_row] = wv.z;
        Bs[l_c4 + 3][l_row] = wv.w;
        __syncthreads();

        #pragma unroll
        for (int kk = 0; kk < BKK; kk++) {
            float ra[TM], rb[TN];
            #pragma unroll
            for (int i = 0; i < TM; i++) ra[i] = As[kk][ty * TM + i];
            #pragma unroll
            for (int j = 0; j < TN; j++) rb[j] = Bs[kk][tx * TN + j];
            #pragma unroll
            for (int i = 0; i < TM; i++)
                #pragma unroll
                for (int j = 0; j < TN; j++)
                    acc[i][j] += ra[i] * rb[j];
        }
    }

    #pragma unroll
    for (int i = 0; i < TM; i++) {
        const int row = bm + ty * TM + i;
        float* crow = C + (size_t)row * N + bn + tx * TN;
        #pragma unroll
        for (int j = 0; j < TN; j += 4) {
            float4 v;
            v.x = acc[i][j + 0] + bias[bn + tx * TN + j + 0];
            v.y = acc[i][j + 1] + bias[bn + tx * TN + j + 1];
            v.z = acc[i][j + 2] + bias[bn + tx * TN + j + 2];
            v.w = acc[i][j + 3] + bias[bn + tx * TN + j + 3];
            *(float4*)&crow[j] = v;
        }
    }
}

// ---------------------------------------------------------------------------
// RoPE: apply rotary embedding to Q and K projections.
// One thread per (b,t,h,pair). pair i in [0,32).
// ---------------------------------------------------------------------------
__global__ void rope_kernel(float* __restrict__ qr, float* __restrict__ kr,
                            const float* __restrict__ qin, const float* __restrict__ kin,
                            const int* __restrict__ pos)
{
    const int idx = blockIdx.x * blockDim.x + threadIdx.x;   // [0, B*T*NH*32)
    if (idx >= B_ * T_ * NH * 32) return;
    const int i = idx & 31;
    const int h = (idx >> 5) & (NH - 1);
    const int t = (idx >> 9) & (T_ - 1);
    const int b = idx >> 20;

    const double inv_freq = pow(10000.0, -(double)i / 32.0);
    const float ang = (float)((double)pos[t] * inv_freq);
    float s, c;
    __sincosf(ang, &s, &c);
    // use accurate versions to keep error small
    c = cosf(ang); s = sinf(ang);

    const size_t base = ((size_t)b * T_ + t) * DM + h * DK + 2 * i;
    const float q1 = qin[base], q2 = qin[base + 1];
    const float k1 = kin[base], k2 = kin[base + 1];
    qr[base]     = q1 * c - q2 * s;
    qr[base + 1] = q1 * s + q2 * c;
    kr[base]     = k1 * c - k2 * s;
    kr[base + 1] = k1 * s + k2 * c;
}

// ---------------------------------------------------------------------------
// Flash attention (causal), fp32.
// Grid: (T/64, NH, B). 64 threads; thread i owns query row qb*64+i.
// Q row in registers; K/V tiles in smem read via broadcast float4.
// ---------------------------------------------------------------------------
__global__ __launch_bounds__(64)
void flash_attn(float* __restrict__ out, const float* __restrict__ Q,
                const float* __restrict__ Kx, const float* __restrict__ V)
{
    const int qb = blockIdx.x;
    const int h  = blockIdx.y;
    const int b  = blockIdx.z;
    const int tid = threadIdx.x;

    __shared__ float Ks[64][DK + 4];
    __shared__ float Vs[64][DK + 4];

    const float* Qbase = Q + ((size_t)b * T_ + qb * 64) * DM + h * DK;

    // Stage Q tile through Ks (coalesced), then copy own row to registers.
    for (int idx = tid; idx < 64 * DK; idx += 64) {
        const int r = idx >> 6, c = idx & 63;
        Ks[r][c] = Qbase[r * DM + c];
    }
    __syncthreads();

    float q[DK], o[DK];
    #pragma unroll
    for (int d = 0; d < DK; d++) { q[d] = Ks[tid][d]; o[d] = 0.f; }

    float m = -1e30f, l = 0.f;
    const int my_row = qb * 64 + tid;
    const float scale = 0.125f;  // 1/sqrt(64)

    for (int kb = 0; kb <= qb; kb++) {
        const float* Kbase = Kx + ((size_t)b * T_ + kb * 64) * DM + h * DK;
        const float* Vbase = V  + ((size_t)b * T_ + kb * 64) * DM + h * DK;
        __syncthreads();
        for (int idx = tid; idx < 64 * DK; idx += 64) {
            const int r = idx >> 6, c = idx & 63;
            Ks[r][c] = Kbase[r * DM + c];
            Vs[r][c] = Vbase[r * DM + c];
        }
        __syncthreads();

        const bool diag = (kb == qb);

        #pragma unroll 1
        for (int jc = 0; jc < 64; jc += 16) {
            float s[16];
            #pragma unroll
            for (int j = 0; j < 16; j++) s[j] = 0.f;

            #pragma unroll 2
            for (int d = 0; d < DK; d += 4) {
                #pragma unroll
                for (int j = 0; j < 16; j++) {
                    const float4 kv = *(const float4*)&Ks[jc + j][d];
                    s[j] += q[d] * kv.x;
                    s[j] += q[d + 1] * kv.y;
                    s[j] += q[d + 2] * kv.z;
                    s[j] += q[d + 3] * kv.w;
                }
            }

            float mloc = -1e30f;
            #pragma unroll
            for (int j = 0; j < 16; j++) {
                s[j] *= scale;
                if (diag && (kb * 64 + jc + j > my_row)) s[j] = -1e30f;
                mloc = fmaxf(mloc, s[j]);
            }
            const float mnew = fmaxf(m, mloc);
            const float corr = __expf(m - mnew);
            l *= corr;
            #pragma unroll
            for (int d = 0; d < DK; d++) o[d] *= corr;

            float p[16];
            #pragma unroll
            for (int j = 0; j < 16; j++) { p[j] = __expf(s[j] - mnew); l += p[j]; }

            #pragma unroll 2
            for (int d = 0; d < DK; d += 4) {
                float a0 = o[d], a1 = o[d + 1], a2 = o[d + 2], a3 = o[d + 3];
                #pragma unroll
                for (int j = 0; j < 16; j++) {
                    const float4 vv = *(const float4*)&Vs[jc + j][d];
                    a0 += p[j] * vv.x;
                    a1 += p[j] * vv.y;
                    a2 += p[j] * vv.z;
                    a3 += p[j] * vv.w;
                }
                o[d] = a0; o[d + 1] = a1; o[d + 2] = a2; o[d + 3] = a3;
            }
            m = mnew;
        }
    }

    const float inv_l = 1.f / l;
    __syncthreads();
    #pragma unroll
    for (int d = 0; d < DK; d++) Ks[tid][d] = o[d] * inv_l;
    __syncthreads();

    float* Obase = out + ((size_t)b * T_ + qb * 64) * DM + h * DK;
    for (int idx = tid; idx < 64 * DK; idx += 64) {
        const int r = idx >> 6, c = idx & 63;
        Obase[r * DM + c] = Ks[r][c];
    }
}

// ---------------------------------------------------------------------------
extern "C" void kernel_launch(void* const* d_in, const int* in_sizes, int n_in,
                              void* d_out, int out_size)
{
    const float* x   = (const float*)d_in[0];
    const int*   pos = (const int*)d_in[1];
    const float* Wq  = (const float*)d_in[2];
    const float* bq  = (const float*)d_in[3];
    const float* Wk  = (const float*)d_in[4];
    const float* bk  = (const float*)d_in[5];
    // d_in[6] = Wv, d_in[7] = bv : unused (reference uses Wq/bq for V)
    const float* Wo  = (const float*)d_in[8];
    const float* bo  = (const float*)d_in[9];
    float* out = (float*)d_out;

    float *QV, *Kp, *Qr, *Kr, *At;
    cudaGetSymbolAddress((void**)&QV, g_QV);
    cudaGetSymbolAddress((void**)&Kp, g_Kp);
    cudaGetSymbolAddress((void**)&Qr, g_Qr);
    cudaGetSymbolAddress((void**)&Kr, g_Kr);
    cudaGetSymbolAddress((void**)&At, g_At);

    const int M = B_ * T_;   // 4096
    dim3 gemm_grid(DM / BN, M / BM);   // (8, 32)

    // Q/V projection (shared) and K projection
    sgemm_nt_bias<<<gemm_grid, 256>>>(QV, x, Wq, bq, M, DM, DM);
    sgemm_nt_bias<<<gemm_grid, 256>>>(Kp, x, Wk, bk, M, DM, DM);

    // RoPE
    const int total_pairs = B_ * T_ * NH * 32;
    rope_kernel<<<(total_pairs + 255) / 256, 256>>>(Qr, Kr, QV, Kp, pos);

    // Causal flash attention (V = pre-RoPE Q projection, per reference)
    flash_attn<<<dim3(T_ / 64, NH, B_), 64>>>(At, Qr, Kr, QV);

    // Output projection
    sgemm_nt_bias<<<gemm_grid, 256>>>(out, At, Wo, bo, M, DM, DM);
}

// round 7
// speedup vs baseline: 2.6044x; 2.6044x over previous
#include <cuda_runtime.h>
#include <math.h>
#include <stdint.h>

#define B_ 2
#define T_ 2048
#define DM 1024
#define NH 16
#define DK 64

// Scratch (device globals; no allocation allowed)
__device__ float g_QV[B_*T_*DM];   // x@Wq.T+bq  (pre-RoPE) == V
__device__ float g_Kp[B_*T_*DM];   // x@Wk.T+bk  (pre-RoPE)
__device__ float g_Qr[B_*T_*DM];   // RoPE(Q)
__device__ float g_Kr[B_*T_*DM];   // RoPE(K)
__device__ float g_At[B_*T_*DM];   // attention heads output [b,t,h*64+d]

__device__ __forceinline__ uint32_t f2tf(float x) {
    uint32_t u;
    asm("cvt.rna.tf32.f32 %0, %1;" : "=r"(u) : "f"(x));
    return u;
}

__device__ __forceinline__ void mma_tf32(float c[4], uint32_t a0, uint32_t a1,
                                         uint32_t a2, uint32_t a3,
                                         uint32_t b0, uint32_t b1) {
    asm volatile(
        "mma.sync.aligned.m16n8k8.row.col.f32.tf32.tf32.f32 "
        "{%0,%1,%2,%3}, {%4,%5,%6,%7}, {%8,%9}, {%0,%1,%2,%3};"
        : "+f"(c[0]), "+f"(c[1]), "+f"(c[2]), "+f"(c[3])
        : "r"(a0), "r"(a1), "r"(a2), "r"(a3), "r"(b0), "r"(b1));
}

// ---------------------------------------------------------------------------
// tf32 tensor-core GEMM: C[m,n] = sum_k A[m,k]*W[n,k] + bias[n]
// BM=BN=128, BK=16, 256 threads (8 warps: 2 M x 4 N), warp tile 64x32,
// double-buffered smem.
// ---------------------------------------------------------------------------
#define GBM 128
#define GBN 128
#define GBK 16

__global__ __launch_bounds__(256, 2)
void gemm_tf32_nt_bias(float* __restrict__ C, const float* __restrict__ A,
                       const float* __restrict__ W, const float* __restrict__ bias,
                       int M, int N, int K)
{
    __shared__ uint32_t As[2][GBK][GBM + 4];
    __shared__ uint32_t Bs[2][GBK][GBN + 4];

    const int tid  = threadIdx.x;
    const int lane = tid & 31;
    const int warp = tid >> 5;
    const int wm   = warp & 1;
    const int wn   = warp >> 1;
    const int bm   = blockIdx.y * GBM;
    const int bn   = blockIdx.x * GBN;

    const int s_row = tid >> 2;
    const int s_col = (tid & 3) * 4;

    float acc[4][4][4];
    #pragma unroll
    for (int i = 0; i < 4; i++)
        #pragma unroll
        for (int j = 0; j < 4; j++)
            #pragma unroll
            for (int f = 0; f < 4; f++) acc[i][j][f] = 0.f;

    const int NI = K / GBK;
    float4 ra0, ra1, rb0, rb1;

    auto load_tile = [&](int k0) {
        ra0 = *(const float4*)&A[(size_t)(bm + s_row)      * K + k0 + s_col];
        ra1 = *(const float4*)&A[(size_t)(bm + 64 + s_row) * K + k0 + s_col];
        rb0 = *(const float4*)&W[(size_t)(bn + s_row)      * K + k0 + s_col];
        rb1 = *(const float4*)&W[(size_t)(bn + 64 + s_row) * K + k0 + s_col];
    };
    auto store_tile = [&](int buf) {
        As[buf][s_col + 0][s_row]      = f2tf(ra0.x);
        As[buf][s_col + 1][s_row]      = f2tf(ra0.y);
        As[buf][s_col + 2][s_row]      = f2tf(ra0.z);
        As[buf][s_col + 3][s_row]      = f2tf(ra0.w);
        As[buf][s_col + 0][64 + s_row] = f2tf(ra1.x);
        As[buf][s_col + 1][64 + s_row] = f2tf(ra1.y);
        As[buf][s_col + 2][64 + s_row] = f2tf(ra1.z);
        As[buf][s_col + 3][64 + s_row] = f2tf(ra1.w);
        Bs[buf][s_col + 0][s_row]      = f2tf(rb0.x);
        Bs[buf][s_col + 1][s_row]      = f2tf(rb0.y);
        Bs[buf][s_col + 2][s_row]      = f2tf(rb0.z);
        Bs[buf][s_col + 3][s_row]      = f2tf(rb0.w);
        Bs[buf][s_col + 0][64 + s_row] = f2tf(rb1.x);
        Bs[buf][s_col + 1][64 + s_row] = f2tf(rb1.y);
        Bs[buf][s_col + 2][64 + s_row] = f2tf(rb1.z);
        Bs[buf][s_col + 3][64 + s_row] = f2tf(rb1.w);
    };

    load_tile(0);
    store_tile(0);
    __syncthreads();

    const int lk = lane & 3;
    const int lq = lane >> 2;

    for (int it = 0; it < NI; it++) {
        const int buf = it & 1;
        if (it + 1 < NI) load_tile((it + 1) * GBK);

        #pragma unroll
        for (int ks = 0; ks < 2; ks++) {
            const int kk = ks * 8;
            uint32_t af[4][4], bf[4][2];
            #pragma unroll
            for (int mt = 0; mt < 4; mt++) {
                const int mm = wm * 64 + mt * 16 + lq;
                af[mt][0] = As[buf][kk + lk][mm];
                af[mt][1] = As[buf][kk + lk][mm + 8];
                af[mt][2] = As[buf][kk + 4 + lk][mm];
                af[mt][3] = As[buf][kk + 4 + lk][mm + 8];
            }
            #pragma unroll
            for (int nt = 0; nt < 4; nt++) {
                const int n0 = wn * 32 + nt * 8 + lq;
                bf[nt][0] = Bs[buf][kk + lk][n0];
                bf[nt][1] = Bs[buf][kk + 4 + lk][n0];
            }
            #pragma unroll
            for (int mt = 0; mt < 4; mt++)
                #pragma unroll
                for (int nt = 0; nt < 4; nt++)
                    mma_tf32(acc[mt][nt], af[mt][0], af[mt][1], af[mt][2], af[mt][3],
                             bf[nt][0], bf[nt][1]);
        }

        if (it + 1 < NI) {
            __syncthreads();
            store_tile(buf ^ 1);
            __syncthreads();
        }
    }

    #pragma unroll
    for (int mt = 0; mt < 4; mt++) {
        const int r0 = bm + wm * 64 + mt * 16 + lq;
        const int r1 = r0 + 8;
        #pragma unroll
        for (int nt = 0; nt < 4; nt++) {
            const int cc = bn + wn * 32 + nt * 8 + 2 * lk;
            const float bx = bias[cc], by = bias[cc + 1];
            float2 v0 = make_float2(acc[mt][nt][0] + bx, acc[mt][nt][1] + by);
            float2 v1 = make_float2(acc[mt][nt][2] + bx, acc[mt][nt][3] + by);
            *(float2*)&C[(size_t)r0 * N + cc] = v0;
            *(float2*)&C[(size_t)r1 * N + cc] = v1;
        }
    }
}

// ---------------------------------------------------------------------------
// RoPE
// ---------------------------------------------------------------------------
__global__ void rope_kernel(float* __restrict__ qr, float* __restrict__ kr,
                            const float* __restrict__ qin, const float* __restrict__ kin,
                            const int* __restrict__ pos)
{
    const int idx = blockIdx.x * blockDim.x + threadIdx.x;
    if (idx >= B_ * T_ * NH * 32) return;
    const int i = idx & 31;
    const int h = (idx >> 5) & (NH - 1);
    const int t = (idx >> 9) & (T_ - 1);
    const int b = idx >> 20;

    const double inv_freq = pow(10000.0, -(double)i / 32.0);
    const float ang = (float)((double)pos[t] * inv_freq);
    const float c = cosf(ang), s = sinf(ang);

    const size_t base = ((size_t)b * T_ + t) * DM + h * DK + 2 * i;
    const float q1 = qin[base], q2 = qin[base + 1];
    const float k1 = kin[base], k2 = kin[base + 1];
    qr[base]     = q1 * c - q2 * s;
    qr[base + 1] = q1 * s + q2 * c;
    kr[base]     = k1 * c - k2 * s;
    kr[base + 1] = k1 * s + k2 * c;
}

// ---------------------------------------------------------------------------
// Flash attention (causal) with tf32 mma.
// Grid (32, NH, B), 128 threads (4 warps). Q-tile 64 rows; warp w owns rows
// 16w..16w+15. K/V tiles of 64 rows. All smem natural row-major:
//   Qs/Ks/Ps stride 68 (frag loads conflict-free), Vs stride 72.
// P round-trips through smem (tf32) between the two mma stages.
// ---------------------------------------------------------------------------
#define QS_STRIDE 68
#define VS_STRIDE 72
#define FLASH_SMEM ((3*64*QS_STRIDE + 64*VS_STRIDE) * 4)

__global__ __launch_bounds__(128)
void flash_attn_mma(float* __restrict__ out, const float* __restrict__ Q,
                    const float* __restrict__ Kx, const float* __restrict__ V)
{
    extern __shared__ uint32_t sm[];
    uint32_t* Qs = sm;                          // [64][68]  tf32
    uint32_t* Ks = Qs + 64 * QS_STRIDE;         // [64][68]  tf32
    uint32_t* Ps = Ks + 64 * QS_STRIDE;         // [64][68]  tf32
    uint32_t* Vs = Ps + 64 * QS_STRIDE;         // [64][72]  tf32

    const int qb = (int)gridDim.x - 1 - (int)blockIdx.x;  // big tiles first
    const int h  = blockIdx.y;
    const int b  = blockIdx.z;
    const int tid  = threadIdx.x;
    const int lane = tid & 31;
    const int warp = tid >> 5;
    const int lk = lane & 3;
    const int lq = lane >> 2;
    const int m0 = warp * 16 + lq;  // local q row for c0/c1 ; +8 for c2/c3

    // ---- stage Q tile (64x64) ----
    const float* Qg = Q + ((size_t)(b * T_ + qb * 64)) * DM + h * DK;
    for (int i = tid; i < 64 * 16; i += 128) {
        const int r = i >> 4, c4 = (i & 15) * 4;
        const float4 v = *(const float4*)&Qg[(size_t)r * DM + c4];
        uint32_t* dst = &Qs[r * QS_STRIDE + c4];
        dst[0] = f2tf(v.x); dst[1] = f2tf(v.y);
        dst[2] = f2tf(v.z); dst[3] = f2tf(v.w);
    }

    float o_acc[8][4];
    #pragma unroll
    for (int dt = 0; dt < 8; dt++)
        #pragma unroll
        for (int f = 0; f < 4; f++) o_acc[dt][f] = 0.f;

    float m0r = -1e30f, m1r = -1e30f, l0 = 0.f, l1 = 0.f;
    const float scale = 0.125f;   // 1/sqrt(64)

    __syncthreads();

    for (int kb = 0; kb <= qb; kb++) {
        __syncthreads();   // all warps done reading prev Ks/Vs
        const float* Kg = Kx + ((size_t)(b * T_ + kb * 64)) * DM + h * DK;
        const float* Vg = V  + ((size_t)(b * T_ + kb * 64)) * DM + h * DK;
        for (int i = tid; i < 64 * 16; i += 128) {
            const int r = i >> 4, c4 = (i & 15) * 4;
            const float4 kv = *(const float4*)&Kg[(size_t)r * DM + c4];
            const float4 vv = *(const float4*)&Vg[(size_t)r * DM + c4];
            uint32_t* kd = &Ks[r * QS_STRIDE + c4];
            kd[0] = f2tf(kv.x); kd[1] = f2tf(kv.y);
            kd[2] = f2tf(kv.z); kd[3] = f2tf(kv.w);
            uint32_t* vd = &Vs[r * VS_STRIDE + c4];
            vd[0] = f2tf(vv.x); vd[1] = f2tf(vv.y);
            vd[2] = f2tf(vv.z); vd[3] = f2tf(vv.w);
        }
        __syncthreads();

        // ---- S = Q @ K^T  (M=16/warp, N=64 -> 8 n-tiles, Kdim=64 -> 8 ksteps)
        float s_acc[8][4];
        #pragma unroll
        for (int nt = 0; nt < 8; nt++)
            #pragma unroll
            for (int f = 0; f < 4; f++) s_acc[nt][f] = 0.f;

        #pragma unroll
        for (int ks = 0; ks < 8; ks++) {
            const int kk = ks * 8;
            const uint32_t a0 = Qs[m0 * QS_STRIDE + kk + lk];
            const uint32_t a1 = Qs[(m0 + 8) * QS_STRIDE + kk + lk];
            const uint32_t a2 = Qs[m0 * QS_STRIDE + kk + 4 + lk];
            const uint32_t a3 = Qs[(m0 + 8) * QS_STRIDE + kk + 4 + lk];
            #pragma unroll
            for (int nt = 0; nt < 8; nt++) {
                const int n0 = nt * 8 + lq;    // local k row
                const uint32_t b0 = Ks[n0 * QS_STRIDE + kk + lk];
                const uint32_t b1 = Ks[n0 * QS_STRIDE + kk + 4 + lk];
                mma_tf32(s_acc[nt], a0, a1, a2, a3, b0, b1);
            }
        }

        // scale + causal mask (only diagonal tile needs masking)
        #pragma unroll
        for (int nt = 0; nt < 8; nt++)
            #pragma unroll
            for (int f = 0; f < 4; f++) s_acc[nt][f] *= scale;

        if (kb == qb) {
            #pragma unroll
            for (int nt = 0; nt < 8; nt++) {
                const int c0 = nt * 8 + 2 * lk;
                if (c0     > m0)     s_acc[nt][0] = -1e30f;
                if (c0 + 1 > m0)     s_acc[nt][1] = -1e30f;
                if (c0     > m0 + 8) s_acc[nt][2] = -1e30f;
                if (c0 + 1 > m0 + 8) s_acc[nt][3] = -1e30f;
            }
        }

        // ---- online softmax (rows lq / lq+8, reduce over 4-lane groups) ----
        float mx0 = -1e30f, mx1 = -1e30f;
        #pragma unroll
        for (int nt = 0; nt < 8; nt++) {
            mx0 = fmaxf(mx0, fmaxf(s_acc[nt][0], s_acc[nt][1]));
            mx1 = fmaxf(mx1, fmaxf(s_acc[nt][2], s_acc[nt][3]));
        }
        mx0 = fmaxf(mx0, __shfl_xor_sync(0xffffffffu, mx0, 1));
        mx0 = fmaxf(mx0, __shfl_xor_sync(0xffffffffu, mx0, 2));
        mx1 = fmaxf(mx1, __shfl_xor_sync(0xffffffffu, mx1, 1));
        mx1 = fmaxf(mx1, __shfl_xor_sync(0xffffffffu, mx1, 2));

        const float mn0 = fmaxf(m0r, mx0);
        const float mn1 = fmaxf(m1r, mx1);
        const float cr0 = __expf(m0r - mn0);
        const float cr1 = __expf(m1r - mn1);
        l0 *= cr0; l1 *= cr1;
        #pragma unroll
        for (int dt = 0; dt < 8; dt++) {
            o_acc[dt][0] *= cr0; o_acc[dt][1] *= cr0;
            o_acc[dt][2] *= cr1; o_acc[dt][3] *= cr1;
        }

        float rs0 = 0.f, rs1 = 0.f;
        #pragma unroll
        for (int nt = 0; nt < 8; nt++) {
            const float p0 = __expf(s_acc[nt][0] - mn0);
            const float p1 = __expf(s_acc[nt][1] - mn0);
            const float p2 = __expf(s_acc[nt][2] - mn1);
            const float p3 = __expf(s_acc[nt][3] - mn1);
            rs0 += p0 + p1; rs1 += p2 + p3;
            const int c0 = nt * 8 + 2 * lk;
            Ps[m0 * QS_STRIDE + c0]           = f2tf(p0);
            Ps[m0 * QS_STRIDE + c0 + 1]       = f2tf(p1);
            Ps[(m0 + 8) * QS_STRIDE + c0]     = f2tf(p2);
            Ps[(m0 + 8) * QS_STRIDE + c0 + 1] = f2tf(p3);
        }
        rs0 += __shfl_xor_sync(0xffffffffu, rs0, 1);
        rs0 += __shfl_xor_sync(0xffffffffu, rs0, 2);
        rs1 += __shfl_xor_sync(0xffffffffu, rs1, 1);
        rs1 += __shfl_xor_sync(0xffffffffu, rs1, 2);
        l0 += rs0; l1 += rs1;
        m0r = mn0; m1r = mn1;

        __syncwarp();   // Ps visible to whole warp before A-frag loads

        // ---- O += P @ V  (Kdim=64 krows -> 8 ksteps, N=64 d -> 8 n-tiles) ----
        #pragma unroll
        for (int ks = 0; ks < 8; ks++) {
            const int kk = ks * 8;
            const uint32_t a0 = Ps[m0 * QS_STRIDE + kk + lk];
            const uint32_t a1 = Ps[(m0 + 8) * QS_STRIDE + kk + lk];
            const uint32_t a2 = Ps[m0 * QS_STRIDE + kk + 4 + lk];
            const uint32_t a3 = Ps[(m0 + 8) * QS_STRIDE + kk + 4 + lk];
            #pragma unroll
            for (int dt = 0; dt < 8; dt++) {
                const int n0 = dt * 8 + lq;    // d column
                const uint32_t b0 = Vs[(kk + lk) * VS_STRIDE + n0];
                const uint32_t b1 = Vs[(kk + 4 + lk) * VS_STRIDE + n0];
                mma_tf32(o_acc[dt], a0, a1, a2, a3, b0, b1);
            }
        }
        __syncwarp();   // PV reads done before next tile's Ps overwrite
    }

    // ---- epilogue ----
    const float inv0 = 1.f / l0;
    const float inv1 = 1.f / l1;
    float* Og = out + ((size_t)(b * T_ + qb * 64)) * DM + h * DK;
    #pragma unroll
    for (int dt = 0; dt < 8; dt++) {
        const int col = dt * 8 + 2 * lk;
        float2 v0 = make_float2(o_acc[dt][0] * inv0, o_acc[dt][1] * inv0);
        float2 v1 = make_float2(o_acc[dt][2] * inv1, o_acc[dt][3] * inv1);
        *(float2*)&Og[(size_t)m0 * DM + col]       = v0;
        *(float2*)&Og[(size_t)(m0 + 8) * DM + col] = v1;
    }
}

// ---------------------------------------------------------------------------
extern "C" void kernel_launch(void* const* d_in, const int* in_sizes, int n_in,
                              void* d_out, int out_size)
{
    const float* x   = (const float*)d_in[0];
    const int*   pos = (const int*)d_in[1];
    const float* Wq  = (const float*)d_in[2];
    const float* bq  = (const float*)d_in[3];
    const float* Wk  = (const float*)d_in[4];
    const float* bk  = (const float*)d_in[5];
    // d_in[6]=Wv, d_in[7]=bv unused (reference uses Wq/bq for V)
    const float* Wo  = (const float*)d_in[8];
    const float* bo  = (const float*)d_in[9];
    float* out = (float*)d_out;

    float *QV, *Kp, *Qr, *Kr, *At;
    cudaGetSymbolAddress((void**)&QV, g_QV);
    cudaGetSymbolAddress((void**)&Kp, g_Kp);
    cudaGetSymbolAddress((void**)&Qr, g_Qr);
    cudaGetSymbolAddress((void**)&Kr, g_Kr);
    cudaGetSymbolAddress((void**)&At, g_At);

    // Idempotent, called every time (no static guards per harness rules).
    cudaFuncSetAttribute(flash_attn_mma,
                         cudaFuncAttributeMaxDynamicSharedMemorySize,
                         FLASH_SMEM);

    const int M = B_ * T_;   // 4096
    dim3 gemm_grid(DM / GBN, M / GBM);   // (8, 32)

    gemm_tf32_nt_bias<<<gemm_grid, 256>>>(QV, x, Wq, bq, M, DM, DM);
    gemm_tf32_nt_bias<<<gemm_grid, 256>>>(Kp, x, Wk, bk, M, DM, DM);

    const int total_pairs = B_ * T_ * NH * 32;
    rope_kernel<<<(total_pairs + 255) / 256, 256>>>(Qr, Kr, QV, Kp, pos);

    flash_attn_mma<<<dim3(T_ / 64, NH, B_), 128, FLASH_SMEM>>>(At, Qr, Kr, QV);

    gemm_tf32_nt_bias<<<gemm_grid, 256>>>(out, At, Wo, bo, M, DM, DM);
}

// round 8
// speedup vs baseline: 2.7159x; 1.0428x over previous
#include <cuda_runtime.h>
#include <math.h>
#include <stdint.h>

#define B_ 2
#define T_ 2048
#define DM 1024
#define NH 16
#define DK 64

// Scratch (device globals; no allocation allowed)
__device__ float g_QV[B_*T_*DM];   // x@Wq.T+bq  (pre-RoPE) == V
__device__ float g_Kp[B_*T_*DM];   // x@Wk.T+bk  (pre-RoPE)
__device__ float g_Qr[B_*T_*DM];   // RoPE(Q)
__device__ float g_Kr[B_*T_*DM];   // RoPE(K)
__device__ float g_At[B_*T_*DM];   // attention heads output [b,t,h*64+d]

__device__ __forceinline__ uint32_t f2tf(float x) {
    uint32_t u;
    asm("cvt.rna.tf32.f32 %0, %1;" : "=r"(u) : "f"(x));
    return u;
}

__device__ __forceinline__ void mma_tf32(float c[4], uint32_t a0, uint32_t a1,
                                         uint32_t a2, uint32_t a3,
                                         uint32_t b0, uint32_t b1) {
    asm volatile(
        "mma.sync.aligned.m16n8k8.row.col.f32.tf32.tf32.f32 "
        "{%0,%1,%2,%3}, {%4,%5,%6,%7}, {%8,%9}, {%0,%1,%2,%3};"
        : "+f"(c[0]), "+f"(c[1]), "+f"(c[2]), "+f"(c[3])
        : "r"(a0), "r"(a1), "r"(a2), "r"(a3), "r"(b0), "r"(b1));
}

// ---------------------------------------------------------------------------
// tf32 GEMM core: C[bm..+128, bn..+128] = A[128,K] @ W[128,K]^T + bias.
// K = DM = 1024 fixed. Smem [m][k] layout, stride 20 words:
//   frag loads addr = row*20 + (kk+lk)  ==> (20*lq + lk) mod 32: conflict-free.
// Double-buffered, ONE __syncthreads per K-tile.
// ---------------------------------------------------------------------------
#define GBK 16
#define SK  20           // smem k-stride (words)
#define GEMM_NI (DM / GBK)

struct GemmSmem { uint32_t As[2][128][SK]; uint32_t Bs[2][128][SK]; };

__device__ __forceinline__ void gemm_core_128x128(
    float* __restrict__ C, const float* __restrict__ A,
    const float* __restrict__ W, const float* __restrict__ bias,
    int bm, int bn, GemmSmem& sm)
{
    const int tid  = threadIdx.x;
    const int lane = tid & 31;
    const int warp = tid >> 5;
    const int wm   = warp & 1;    // 2 warps along M (64 rows each)
    const int wn   = warp >> 1;   // 4 warps along N (32 cols each)
    const int lk   = lane & 3;
    const int lq   = lane >> 2;

    // staging: thread handles row (tid>>1), cols (tid&1)*8 .. +7 (2 float4)
    const int s_row = tid >> 1;
    const int s_c8  = (tid & 1) * 8;

    const float* Arow = A + (size_t)(bm + s_row) * DM + s_c8;
    const float* Wrow = W + (size_t)(bn + s_row) * DM + s_c8;

    float acc[4][4][4];
    #pragma unroll
    for (int i = 0; i < 4; i++)
        #pragma unroll
        for (int j = 0; j < 4; j++)
            #pragma unroll
            for (int f = 0; f < 4; f++) acc[i][j][f] = 0.f;

    float4 ra0, ra1, rb0, rb1;
    auto load_tile = [&](int k0) {
        ra0 = *(const float4*)&Arow[k0];
        ra1 = *(const float4*)&Arow[k0 + 4];
        rb0 = *(const float4*)&Wrow[k0];
        rb1 = *(const float4*)&Wrow[k0 + 4];
    };
    auto store_tile = [&](int buf) {
        uint4 ua0 = make_uint4(f2tf(ra0.x), f2tf(ra0.y), f2tf(ra0.z), f2tf(ra0.w));
        uint4 ua1 = make_uint4(f2tf(ra1.x), f2tf(ra1.y), f2tf(ra1.z), f2tf(ra1.w));
        uint4 ub0 = make_uint4(f2tf(rb0.x), f2tf(rb0.y), f2tf(rb0.z), f2tf(rb0.w));
        uint4 ub1 = make_uint4(f2tf(rb1.x), f2tf(rb1.y), f2tf(rb1.z), f2tf(rb1.w));
        *(uint4*)&sm.As[buf][s_row][s_c8]     = ua0;
        *(uint4*)&sm.As[buf][s_row][s_c8 + 4] = ua1;
        *(uint4*)&sm.Bs[buf][s_row][s_c8]     = ub0;
        *(uint4*)&sm.Bs[buf][s_row][s_c8 + 4] = ub1;
    };

    load_tile(0);
    store_tile(0);
    __syncthreads();

    for (int it = 0; it < GEMM_NI; it++) {
        const int buf = it & 1;
        if (it + 1 < GEMM_NI) load_tile((it + 1) * GBK);

        #pragma unroll
        for (int ks = 0; ks < 2; ks++) {
            const int kk = ks * 8;
            uint32_t af[4][4], bf[4][2];
            #pragma unroll
            for (int mt = 0; mt < 4; mt++) {
                const int mm = wm * 64 + mt * 16 + lq;
                af[mt][0] = sm.As[buf][mm][kk + lk];
                af[mt][1] = sm.As[buf][mm + 8][kk + lk];
                af[mt][2] = sm.As[buf][mm][kk + 4 + lk];
                af[mt][3] = sm.As[buf][mm + 8][kk + 4 + lk];
            }
            #pragma unroll
            for (int nt = 0; nt < 4; nt++) {
                const int n0 = wn * 32 + nt * 8 + lq;
                bf[nt][0] = sm.Bs[buf][n0][kk + lk];
                bf[nt][1] = sm.Bs[buf][n0][kk + 4 + lk];
            }
            #pragma unroll
            for (int mt = 0; mt < 4; mt++)
                #pragma unroll
                for (int nt = 0; nt < 4; nt++)
                    mma_tf32(acc[mt][nt], af[mt][0], af[mt][1], af[mt][2], af[mt][3],
                             bf[nt][0], bf[nt][1]);
        }

        // Write NEXT tile into the other buffer; safe without a pre-barrier:
        // buf^1 was last read before the barrier at the end of iter it-1.
        if (it + 1 < GEMM_NI) store_tile(buf ^ 1);
        __syncthreads();
    }

    // epilogue
    #pragma unroll
    for (int mt = 0; mt < 4; mt++) {
        const int r0 = bm + wm * 64 + mt * 16 + lq;
        const int r1 = r0 + 8;
        #pragma unroll
        for (int nt = 0; nt < 4; nt++) {
            const int cc = bn + wn * 32 + nt * 8 + 2 * lk;
            const float bx = bias[cc], by = bias[cc + 1];
            float2 v0 = make_float2(acc[mt][nt][0] + bx, acc[mt][nt][1] + by);
            float2 v1 = make_float2(acc[mt][nt][2] + bx, acc[mt][nt][3] + by);
            *(float2*)&C[(size_t)r0 * DM + cc] = v0;
            *(float2*)&C[(size_t)r1 * DM + cc] = v1;
        }
    }
}

// Fused Q & K projections: grid (16, 32). Blocks 0..7 of x -> Q, 8..15 -> K.
__global__ __launch_bounds__(256, 2)
void gemm_qk(float* __restrict__ Cq, float* __restrict__ Ck,
             const float* __restrict__ A,
             const float* __restrict__ Wq, const float* __restrict__ Wk,
             const float* __restrict__ bq, const float* __restrict__ bk)
{
    __shared__ GemmSmem sm;
    const int nb = blockIdx.x;
    const bool is_q = nb < 8;
    float* C = is_q ? Cq : Ck;
    const float* W = is_q ? Wq : Wk;
    const float* bias = is_q ? bq : bk;
    const int bn = (nb & 7) * 128;
    const int bm = blockIdx.y * 128;
    gemm_core_128x128(C, A, W, bias, bm, bn, sm);
}

// Single GEMM (output projection): grid (8, 32).
__global__ __launch_bounds__(256, 2)
void gemm_single(float* __restrict__ C, const float* __restrict__ A,
                 const float* __restrict__ W, const float* __restrict__ bias)
{
    __shared__ GemmSmem sm;
    gemm_core_128x128(C, A, W, bias, blockIdx.y * 128, blockIdx.x * 128, sm);
}

// ---------------------------------------------------------------------------
// RoPE
// ---------------------------------------------------------------------------
__global__ void rope_kernel(float* __restrict__ qr, float* __restrict__ kr,
                            const float* __restrict__ qin, const float* __restrict__ kin,
                            const int* __restrict__ pos)
{
    const int idx = blockIdx.x * blockDim.x + threadIdx.x;
    if (idx >= B_ * T_ * NH * 32) return;
    const int i = idx & 31;
    const int h = (idx >> 5) & (NH - 1);
    const int t = (idx >> 9) & (T_ - 1);
    const int b = idx >> 20;

    const double inv_freq = pow(10000.0, -(double)i / 32.0);
    const float ang = (float)((double)pos[t] * inv_freq);
    const float c = cosf(ang), s = sinf(ang);

    const size_t base = ((size_t)b * T_ + t) * DM + h * DK + 2 * i;
    const float q1 = qin[base], q2 = qin[base + 1];
    const float k1 = kin[base], k2 = kin[base + 1];
    qr[base]     = q1 * c - q2 * s;
    qr[base + 1] = q1 * s + q2 * c;
    kr[base]     = k1 * c - k2 * s;
    kr[base + 1] = k1 * s + k2 * c;
}

// ---------------------------------------------------------------------------
// Flash attention (causal) with tf32 mma — UNCHANGED from R7 (passed, 214us).
// ---------------------------------------------------------------------------
#define QS_STRIDE 68
#define VS_STRIDE 72
#define FLASH_SMEM ((3*64*QS_STRIDE + 64*VS_STRIDE) * 4)

__global__ __launch_bounds__(128)
void flash_attn_mma(float* __restrict__ out, const float* __restrict__ Q,
                    const float* __restrict__ Kx, const float* __restrict__ V)
{
    extern __shared__ uint32_t smf[];
    uint32_t* Qs = smf;                         // [64][68]  tf32
    uint32_t* Ks = Qs + 64 * QS_STRIDE;         // [64][68]  tf32
    uint32_t* Ps = Ks + 64 * QS_STRIDE;         // [64][68]  tf32
    uint32_t* Vs = Ps + 64 * QS_STRIDE;         // [64][72]  tf32

    const int qb = (int)gridDim.x - 1 - (int)blockIdx.x;  // big tiles first
    const int h  = blockIdx.y;
    const int b  = blockIdx.z;
    const int tid  = threadIdx.x;
    const int lane = tid & 31;
    const int warp = tid >> 5;
    const int lk = lane & 3;
    const int lq = lane >> 2;
    const int m0 = warp * 16 + lq;

    const float* Qg = Q + ((size_t)(b * T_ + qb * 64)) * DM + h * DK;
    for (int i = tid; i < 64 * 16; i += 128) {
        const int r = i >> 4, c4 = (i & 15) * 4;
        const float4 v = *(const float4*)&Qg[(size_t)r * DM + c4];
        uint32_t* dst = &Qs[r * QS_STRIDE + c4];
        dst[0] = f2tf(v.x); dst[1] = f2tf(v.y);
        dst[2] = f2tf(v.z); dst[3] = f2tf(v.w);
    }

    float o_acc[8][4];
    #pragma unroll
    for (int dt = 0; dt < 8; dt++)
        #pragma unroll
        for (int f = 0; f < 4; f++) o_acc[dt][f] = 0.f;

    float m0r = -1e30f, m1r = -1e30f, l0 = 0.f, l1 = 0.f;
    const float scale = 0.125f;

    __syncthreads();

    for (int kb = 0; kb <= qb; kb++) {
        __syncthreads();
        const float* Kg = Kx + ((size_t)(b * T_ + kb * 64)) * DM + h * DK;
        const float* Vg = V  + ((size_t)(b * T_ + kb * 64)) * DM + h * DK;
        for (int i = tid; i < 64 * 16; i += 128) {
            const int r = i >> 4, c4 = (i & 15) * 4;
            const float4 kv = *(const float4*)&Kg[(size_t)r * DM + c4];
            const float4 vv = *(const float4*)&Vg[(size_t)r * DM + c4];
            uint32_t* kd = &Ks[r * QS_STRIDE + c4];
            kd[0] = f2tf(kv.x); kd[1] = f2tf(kv.y);
            kd[2] = f2tf(kv.z); kd[3] = f2tf(kv.w);
            uint32_t* vd = &Vs[r * VS_STRIDE + c4];
            vd[0] = f2tf(vv.x); vd[1] = f2tf(vv.y);
            vd[2] = f2tf(vv.z); vd[3] = f2tf(vv.w);
        }
        __syncthreads();

        float s_acc[8][4];
        #pragma unroll
        for (int nt = 0; nt < 8; nt++)
            #pragma unroll
            for (int f = 0; f < 4; f++) s_acc[nt][f] = 0.f;

        #pragma unroll
        for (int ks = 0; ks < 8; ks++) {
            const int kk = ks * 8;
            const uint32_t a0 = Qs[m0 * QS_STRIDE + kk + lk];
            const uint32_t a1 = Qs[(m0 + 8) * QS_STRIDE + kk + lk];
            const uint32_t a2 = Qs[m0 * QS_STRIDE + kk + 4 + lk];
            const uint32_t a3 = Qs[(m0 + 8) * QS_STRIDE + kk + 4 + lk];
            #pragma unroll
            for (int nt = 0; nt < 8; nt++) {
                const int n0 = nt * 8 + lq;
                const uint32_t b0 = Ks[n0 * QS_STRIDE + kk + lk];
                const uint32_t b1 = Ks[n0 * QS_STRIDE + kk + 4 + lk];
                mma_tf32(s_acc[nt], a0, a1, a2, a3, b0, b1);
            }
        }

        #pragma unroll
        for (int nt = 0; nt < 8; nt++)
            #pragma unroll
            for (int f = 0; f < 4; f++) s_acc[nt][f] *= scale;

        if (kb == qb) {
            #pragma unroll
            for (int nt = 0; nt < 8; nt++) {
                const int c0 = nt * 8 + 2 * lk;
                if (c0     > m0)     s_acc[nt][0] = -1e30f;
                if (c0 + 1 > m0)     s_acc[nt][1] = -1e30f;
                if (c0     > m0 + 8) s_acc[nt][2] = -1e30f;
                if (c0 + 1 > m0 + 8) s_acc[nt][3] = -1e30f;
            }
        }

        float mx0 = -1e30f, mx1 = -1e30f;
        #pragma unroll
        for (int nt = 0; nt < 8; nt++) {
            mx0 = fmaxf(mx0, fmaxf(s_acc[nt][0], s_acc[nt][1]));
            mx1 = fmaxf(mx1, fmaxf(s_acc[nt][2], s_acc[nt][3]));
        }
        mx0 = fmaxf(mx0, __shfl_xor_sync(0xffffffffu, mx0, 1));
        mx0 = fmaxf(mx0, __shfl_xor_sync(0xffffffffu, mx0, 2));
        mx1 = fmaxf(mx1, __shfl_xor_sync(0xffffffffu, mx1, 1));
        mx1 = fmaxf(mx1, __shfl_xor_sync(0xffffffffu, mx1, 2));

        const float mn0 = fmaxf(m0r, mx0);
        const float mn1 = fmaxf(m1r, mx1);
        const float cr0 = __expf(m0r - mn0);
        const float cr1 = __expf(m1r - mn1);
        l0 *= cr0; l1 *= cr1;
        #pragma unroll
        for (int dt = 0; dt < 8; dt++) {
            o_acc[dt][0] *= cr0; o_acc[dt][1] *= cr0;
            o_acc[dt][2] *= cr1; o_acc[dt][3] *= cr1;
        }

        float rs0 = 0.f, rs1 = 0.f;
        #pragma unroll
        for (int nt = 0; nt < 8; nt++) {
            const float p0 = __expf(s_acc[nt][0] - mn0);
            const float p1 = __expf(s_acc[nt][1] - mn0);
            const float p2 = __expf(s_acc[nt][2] - mn1);
            const float p3 = __expf(s_acc[nt][3] - mn1);
            rs0 += p0 + p1; rs1 += p2 + p3;
            const int c0 = nt * 8 + 2 * lk;
            Ps[m0 * QS_STRIDE + c0]           = f2tf(p0);
            Ps[m0 * QS_STRIDE + c0 + 1]       = f2tf(p1);
            Ps[(m0 + 8) * QS_STRIDE + c0]     = f2tf(p2);
            Ps[(m0 + 8) * QS_STRIDE + c0 + 1] = f2tf(p3);
        }
        rs0 += __shfl_xor_sync(0xffffffffu, rs0, 1);
        rs0 += __shfl_xor_sync(0xffffffffu, rs0, 2);
        rs1 += __shfl_xor_sync(0xffffffffu, rs1, 1);
        rs1 += __shfl_xor_sync(0xffffffffu, rs1, 2);
        l0 += rs0; l1 += rs1;
        m0r = mn0; m1r = mn1;

        __syncwarp();

        #pragma unroll
        for (int ks = 0; ks < 8; ks++) {
            const int kk = ks * 8;
            const uint32_t a0 = Ps[m0 * QS_STRIDE + kk + lk];
            const uint32_t a1 = Ps[(m0 + 8) * QS_STRIDE + kk + lk];
            const uint32_t a2 = Ps[m0 * QS_STRIDE + kk + 4 + lk];
            const uint32_t a3 = Ps[(m0 + 8) * QS_STRIDE + kk + 4 + lk];
            #pragma unroll
            for (int dt = 0; dt < 8; dt++) {
                const int n0 = dt * 8 + lq;
                const uint32_t b0 = Vs[(kk + lk) * VS_STRIDE + n0];
                const uint32_t b1 = Vs[(kk + 4 + lk) * VS_STRIDE + n0];
                mma_tf32(o_acc[dt], a0, a1, a2, a3, b0, b1);
            }
        }
        __syncwarp();
    }

    const float inv0 = 1.f / l0;
    const float inv1 = 1.f / l1;
    float* Og = out + ((size_t)(b * T_ + qb * 64)) * DM + h * DK;
    #pragma unroll
    for (int dt = 0; dt < 8; dt++) {
        const int col = dt * 8 + 2 * lk;
        float2 v0 = make_float2(o_acc[dt][0] * inv0, o_acc[dt][1] * inv0);
        float2 v1 = make_float2(o_acc[dt][2] * inv1, o_acc[dt][3] * inv1);
        *(float2*)&Og[(size_t)m0 * DM + col]       = v0;
        *(float2*)&Og[(size_t)(m0 + 8) * DM + col] = v1;
    }
}

// ---------------------------------------------------------------------------
extern "C" void kernel_launch(void* const* d_in, const int* in_sizes, int n_in,
                              void* d_out, int out_size)
{
    const float* x   = (const float*)d_in[0];
    const int*   pos = (const int*)d_in[1];
    const float* Wq  = (const float*)d_in[2];
    const float* bq  = (const float*)d_in[3];
    const float* Wk  = (const float*)d_in[4];
    const float* bk  = (const float*)d_in[5];
    // d_in[6]=Wv, d_in[7]=bv unused (reference uses Wq/bq for V)
    const float* Wo  = (const float*)d_in[8];
    const float* bo  = (const float*)d_in[9];
    float* out = (float*)d_out;

    float *QV, *Kp, *Qr, *Kr, *At;
    cudaGetSymbolAddress((void**)&QV, g_QV);
    cudaGetSymbolAddress((void**)&Kp, g_Kp);
    cudaGetSymbolAddress((void**)&Qr, g_Qr);
    cudaGetSymbolAddress((void**)&Kr, g_Kr);
    cudaGetSymbolAddress((void**)&At, g_At);

    // Idempotent, called every time (no static guards per harness rules).
    cudaFuncSetAttribute(flash_attn_mma,
                         cudaFuncAttributeMaxDynamicSharedMemorySize,
                         FLASH_SMEM);

    // Fused Q+K projections: grid (16, 32)
    gemm_qk<<<dim3(16, 32), 256>>>(QV, Kp, x, Wq, Wk, bq, bk);

    const int total_pairs = B_ * T_ * NH * 32;
    rope_kernel<<<(total_pairs + 255) / 256, 256>>>(Qr, Kr, QV, Kp, pos);

    flash_attn_mma<<<dim3(T_ / 64, NH, B_), 128, FLASH_SMEM>>>(At, Qr, Kr, QV);

    // Output projection: grid (8, 32)
    gemm_single<<<dim3(8, 32), 256>>>(out, At, Wo, bo);
}

// round 14
// speedup vs baseline: 3.7081x; 1.3654x over previous
#include <cuda_runtime.h>
#include <math.h>
#include <stdint.h>

#define B_ 2
#define T_ 2048
#define DM 1024
#define NH 16
#define DK 64

// Scratch (device globals; no allocation allowed)
__device__ float g_QV[B_*T_*DM];   // x@Wq.T+bq  (pre-RoPE) == V
__device__ float g_Qr[B_*T_*DM];   // RoPE(Q)
__device__ float g_Kr[B_*T_*DM];   // RoPE(K)
__device__ float g_At[B_*T_*DM];   // attention heads output [b,t,h*64+d]

__device__ __forceinline__ uint32_t f2tf(float x) {
    uint32_t u;
    asm("cvt.rna.tf32.f32 %0, %1;" : "=r"(u) : "f"(x));
    return u;
}

__device__ __forceinline__ void mma_tf32(float c[4], uint32_t a0, uint32_t a1,
                                         uint32_t a2, uint32_t a3,
                                         uint32_t b0, uint32_t b1) {
    asm volatile(
        "mma.sync.aligned.m16n8k8.row.col.f32.tf32.tf32.f32 "
        "{%0,%1,%2,%3}, {%4,%5,%6,%7}, {%8,%9}, {%0,%1,%2,%3};"
        : "+f"(c[0]), "+f"(c[1]), "+f"(c[2]), "+f"(c[3])
        : "r"(a0), "r"(a1), "r"(a2), "r"(a3), "r"(b0), "r"(b1));
}

// ---------------------------------------------------------------------------
// tf32 GEMM core (R8 mainloop, unchanged). Epilogue modes:
//   0: C = acc + bias
//   1: C = acc + bias (raw)   AND   C2 = RoPE(acc + bias)
//   2: C2 = RoPE(acc + bias) only
// RoPE math is bit-identical to the old rope_kernel (double pow, cosf/sinf).
// ---------------------------------------------------------------------------
#define GBK 16
#define SK  20
#define GEMM_NI (DM / GBK)

struct GemmSmem { uint32_t As[2][128][SK]; uint32_t Bs[2][128][SK]; };

__device__ __forceinline__ void gemm_core_128x128(
    float* __restrict__ C, float* __restrict__ C2,
    const float* __restrict__ A, const float* __restrict__ W,
    const float* __restrict__ bias, const int* __restrict__ pos,
    int mode, int bm, int bn, GemmSmem& sm)
{
    const int tid  = threadIdx.x;
    const int lane = tid & 31;
    const int warp = tid >> 5;
    const int wm   = warp & 1;
    const int wn   = warp >> 1;
    const int lk   = lane & 3;
    const int lq   = lane >> 2;

    const int s_row = tid >> 1;
    const int s_c8  = (tid & 1) * 8;

    const float* Arow = A + (size_t)(bm + s_row) * DM + s_c8;
    const float* Wrow = W + (size_t)(bn + s_row) * DM + s_c8;

    float acc[4][4][4];
    #pragma unroll
    for (int i = 0; i < 4; i++)
        #pragma unroll
        for (int j = 0; j < 4; j++)
            #pragma unroll
            for (int f = 0; f < 4; f++) acc[i][j][f] = 0.f;

    float4 ra0, ra1, rb0, rb1;
    auto load_tile = [&](int k0) {
        ra0 = *(const float4*)&Arow[k0];
        ra1 = *(const float4*)&Arow[k0 + 4];
        rb0 = *(const float4*)&Wrow[k0];
        rb1 = *(const float4*)&Wrow[k0 + 4];
    };
    auto store_tile = [&](int buf) {
        uint4 ua0 = make_uint4(f2tf(ra0.x), f2tf(ra0.y), f2tf(ra0.z), f2tf(ra0.w));
        uint4 ua1 = make_uint4(f2tf(ra1.x), f2tf(ra1.y), f2tf(ra1.z), f2tf(ra1.w));
        uint4 ub0 = make_uint4(f2tf(rb0.x), f2tf(rb0.y), f2tf(rb0.z), f2tf(rb0.w));
        uint4 ub1 = make_uint4(f2tf(rb1.x), f2tf(rb1.y), f2tf(rb1.z), f2tf(rb1.w));
        *(uint4*)&sm.As[buf][s_row][s_c8]     = ua0;
        *(uint4*)&sm.As[buf][s_row][s_c8 + 4] = ua1;
        *(uint4*)&sm.Bs[buf][s_row][s_c8]     = ub0;
        *(uint4*)&sm.Bs[buf][s_row][s_c8 + 4] = ub1;
    };

    load_tile(0);
    store_tile(0);
    __syncthreads();

    for (int it = 0; it < GEMM_NI; it++) {
        const int buf = it & 1;
        if (it + 1 < GEMM_NI) load_tile((it + 1) * GBK);

        #pragma unroll
        for (int ks = 0; ks < 2; ks++) {
            const int kk = ks * 8;
            uint32_t af[4][4], bf[4][2];
            #pragma unroll
            for (int mt = 0; mt < 4; mt++) {
                const int mm = wm * 64 + mt * 16 + lq;
                af[mt][0] = sm.As[buf][mm][kk + lk];
                af[mt][1] = sm.As[buf][mm + 8][kk + lk];
                af[mt][2] = sm.As[buf][mm][kk + 4 + lk];
                af[mt][3] = sm.As[buf][mm + 8][kk + 4 + lk];
            }
            #pragma unroll
            for (int nt = 0; nt < 4; nt++) {
                const int n0 = wn * 32 + nt * 8 + lq;
                bf[nt][0] = sm.Bs[buf][n0][kk + lk];
                bf[nt][1] = sm.Bs[buf][n0][kk + 4 + lk];
            }
            #pragma unroll
            for (int mt = 0; mt < 4; mt++)
                #pragma unroll
                for (int nt = 0; nt < 4; nt++)
                    mma_tf32(acc[mt][nt], af[mt][0], af[mt][1], af[mt][2], af[mt][3],
                             bf[nt][0], bf[nt][1]);
        }

        if (it + 1 < GEMM_NI) store_tile(buf ^ 1);
        __syncthreads();
    }

    // ---- epilogue ----
    if (mode == 0) {
        #pragma unroll
        for (int mt = 0; mt < 4; mt++) {
            const int r0 = bm + wm * 64 + mt * 16 + lq;
            const int r1 = r0 + 8;
            #pragma unroll
            for (int nt = 0; nt < 4; nt++) {
                const int cc = bn + wn * 32 + nt * 8 + 2 * lk;
                const float bx = bias[cc], by = bias[cc + 1];
                float2 v0 = make_float2(acc[mt][nt][0] + bx, acc[mt][nt][1] + by);
                float2 v1 = make_float2(acc[mt][nt][2] + bx, acc[mt][nt][3] + by);
                *(float2*)&C[(size_t)r0 * DM + cc] = v0;
                *(float2*)&C[(size_t)r1 * DM + cc] = v1;
            }
        }
    } else {
        // RoPE epilogue. Pair index i = (col within head)/2, identical math
        // to the old rope_kernel.
        double invf[4];
        #pragma unroll
        for (int nt = 0; nt < 4; nt++) {
            const int i = ((wn * 32 + nt * 8 + 2 * lk) & 63) >> 1;
            invf[nt] = pow(10000.0, -(double)i / 32.0);
        }
        #pragma unroll
        for (int mt = 0; mt < 4; mt++) {
            const int r0 = bm + wm * 64 + mt * 16 + lq;
            const int r1 = r0 + 8;
            const int p0 = pos[r0 & (T_ - 1)];
            const int p1 = pos[r1 & (T_ - 1)];
            #pragma unroll
            for (int nt = 0; nt < 4; nt++) {
                const int cc = bn + wn * 32 + nt * 8 + 2 * lk;
                const float bx = bias[cc], by = bias[cc + 1];
                const float x0 = acc[mt][nt][0] + bx, y0 = acc[mt][nt][1] + by;
                const float x1 = acc[mt][nt][2] + bx, y1 = acc[mt][nt][3] + by;
                if (mode == 1) {
                    *(float2*)&C[(size_t)r0 * DM + cc] = make_float2(x0, y0);
                    *(float2*)&C[(size_t)r1 * DM + cc] = make_float2(x1, y1);
                }
                const float a0 = (float)((double)p0 * invf[nt]);
                const float a1 = (float)((double)p1 * invf[nt]);
                const float c0 = cosf(a0), s0 = sinf(a0);
                const float c1 = cosf(a1), s1 = sinf(a1);
                *(float2*)&C2[(size_t)r0 * DM + cc] =
                    make_float2(x0 * c0 - y0 * s0, x0 * s0 + y0 * c0);
                *(float2*)&C2[(size_t)r1 * DM + cc] =
                    make_float2(x1 * c1 - y1 * s1, x1 * s1 + y1 * c1);
            }
        }
    }
}

// Fused Q & K projections + RoPE: grid (16, 32). x-blocks 0..7 -> Q, 8..15 -> K.
__global__ __launch_bounds__(256, 2)
void gemm_qk(float* __restrict__ Cqv, float* __restrict__ Cqr,
             float* __restrict__ Ckr, const float* __restrict__ A,
             const float* __restrict__ Wq, const float* __restrict__ Wk,
             const float* __restrict__ bq, const float* __restrict__ bk,
             const int* __restrict__ pos)
{
    __shared__ GemmSmem sm;
    const int nb = blockIdx.x;
    const bool is_q = nb < 8;
    const int bn = (nb & 7) * 128;
    const int bm = blockIdx.y * 128;
    if (is_q)
        gemm_core_128x128(Cqv, Cqr, A, Wq, bq, pos, 1, bm, bn, sm);
    else
        gemm_core_128x128(Ckr, Ckr, A, Wk, bk, pos, 2, bm, bn, sm);
}

// Output projection: grid (8, 32).
__global__ __launch_bounds__(256, 2)
void gemm_single(float* __restrict__ C, const float* __restrict__ A,
                 const float* __restrict__ W, const float* __restrict__ bias)
{
    __shared__ GemmSmem sm;
    gemm_core_128x128(C, C, A, W, bias, (const int*)nullptr, 0,
                      blockIdx.y * 128, blockIdx.x * 128, sm);
}

// ---------------------------------------------------------------------------
// Flash attention (causal), tf32 mma, K/V double-buffered.
// Grid (32, NH, B), 128 threads (4 warps). Smem (words):
//   Qs[64][68] @0, Ps[64][68] @4352, Ks[2][64][68] @8704, Vs[2][64][72] @17408
// One __syncthreads per kv-iter; next tile staged in registers during compute.
// ---------------------------------------------------------------------------
#define QS_STRIDE 68
#define VS_STRIDE 72
#define KS_OFF 8704
#define VS_OFF 17408
#define FLASH_SMEM ((4352 + 4352 + 2*4352 + 2*4608) * 4)

__global__ __launch_bounds__(128)
void flash_attn_mma(float* __restrict__ out, const float* __restrict__ Q,
                    const float* __restrict__ Kx, const float* __restrict__ V)
{
    extern __shared__ uint32_t smf[];
    uint32_t* Qs = smf;
    uint32_t* Ps = smf + 4352;

    const int qb = (int)gridDim.x - 1 - (int)blockIdx.x;  // big tiles first
    const int h  = blockIdx.y;
    const int b  = blockIdx.z;
    const int tid  = threadIdx.x;
    const int lane = tid & 31;
    const int warp = tid >> 5;
    const int lk = lane & 3;
    const int lq = lane >> 2;
    const int m0 = warp * 16 + lq;

    // ---- stage Q tile ----
    const float* Qg = Q + ((size_t)(b * T_ + qb * 64)) * DM + h * DK;
    #pragma unroll
    for (int j = 0; j < 8; j++) {
        const int idx = tid + 128 * j;
        const int r = idx >> 4, c4 = (idx & 15) * 4;
        const float4 v = *(const float4*)&Qg[(size_t)r * DM + c4];
        uint32_t* dst = &Qs[r * QS_STRIDE + c4];
        dst[0] = f2tf(v.x); dst[1] = f2tf(v.y);
        dst[2] = f2tf(v.z); dst[3] = f2tf(v.w);
    }

    float4 kreg[8], vreg[8];
    auto load_kv = [&](int kb) {
        const float* Kg = Kx + ((size_t)(b * T_ + kb * 64)) * DM + h * DK;
        const float* Vg = V  + ((size_t)(b * T_ + kb * 64)) * DM + h * DK;
        #pragma unroll
        for (int j = 0; j < 8; j++) {
            const int idx = tid + 128 * j;
            const int r = idx >> 4, c4 = (idx & 15) * 4;
            kreg[j] = *(const float4*)&Kg[(size_t)r * DM + c4];
            vreg[j] = *(const float4*)&Vg[(size_t)r * DM + c4];
        }
    };
    auto store_kv = [&](int buf) {
        uint32_t* Kb = smf + KS_OFF + buf * 4352;
        uint32_t* Vb = smf + VS_OFF + buf * 4608;
        #pragma unroll
        for (int j = 0; j < 8; j++) {
            const int idx = tid + 128 * j;
            const int r = idx >> 4, c4 = (idx & 15) * 4;
            uint32_t* kd = &Kb[r * QS_STRIDE + c4];
            kd[0] = f2tf(kreg[j].x); kd[1] = f2tf(kreg[j].y);
            kd[2] = f2tf(kreg[j].z); kd[3] = f2tf(kreg[j].w);
            uint32_t* vd = &Vb[r * VS_STRIDE + c4];
            vd[0] = f2tf(vreg[j].x); vd[1] = f2tf(vreg[j].y);
            vd[2] = f2tf(vreg[j].z); vd[3] = f2tf(vreg[j].w);
        }
    };

    float o_acc[8][4];
    #pragma unroll
    for (int dt = 0; dt < 8; dt++)
        #pragma unroll
        for (int f = 0; f < 4; f++) o_acc[dt][f] = 0.f;

    float m0r = -1e30f, m1r = -1e30f, l0 = 0.f, l1 = 0.f;
    const float scale = 0.125f;

    load_kv(0);
    store_kv(0);
    __syncthreads();

    for (int kb = 0; kb <= qb; kb++) {
        const int buf = kb & 1;
        if (kb < qb) load_kv(kb + 1);

        const uint32_t* Kb = smf + KS_OFF + buf * 4352;
        const uint32_t* Vb = smf + VS_OFF + buf * 4608;

        float s_acc[8][4];
        #pragma unroll
        for (int nt = 0; nt < 8; nt++)
            #pragma unroll
            for (int f = 0; f < 4; f++) s_acc[nt][f] = 0.f;

        #pragma unroll
        for (int ks = 0; ks < 8; ks++) {
            const int kk = ks * 8;
            const uint32_t a0 = Qs[m0 * QS_STRIDE + kk + lk];
            const uint32_t a1 = Qs[(m0 + 8) * QS_STRIDE + kk + lk];
            const uint32_t a2 = Qs[m0 * QS_STRIDE + kk + 4 + lk];
            const uint32_t a3 = Qs[(m0 + 8) * QS_STRIDE + kk + 4 + lk];
            #pragma unroll
            for (int nt = 0; nt < 8; nt++) {
                const int n0 = nt * 8 + lq;
                const uint32_t b0 = Kb[n0 * QS_STRIDE + kk + lk];
                const uint32_t b1 = Kb[n0 * QS_STRIDE + kk + 4 + lk];
                mma_tf32(s_acc[nt], a0, a1, a2, a3, b0, b1);
            }
        }

        #pragma unroll
        for (int nt = 0; nt < 8; nt++)
            #pragma unroll
            for (int f = 0; f < 4; f++) s_acc[nt][f] *= scale;

        if (kb == qb) {
            #pragma unroll
            for (int nt = 0; nt < 8; nt++) {
                const int c0 = nt * 8 + 2 * lk;
                if (c0     > m0)     s_acc[nt][0] = -1e30f;
                if (c0 + 1 > m0)     s_acc[nt][1] = -1e30f;
                if (c0     > m0 + 8) s_acc[nt][2] = -1e30f;
                if (c0 + 1 > m0 + 8) s_acc[nt][3] = -1e30f;
            }
        }

        float mx0 = -1e30f, mx1 = -1e30f;
        #pragma unroll
        for (int nt = 0; nt < 8; nt++) {
            mx0 = fmaxf(mx0, fmaxf(s_acc[nt][0], s_acc[nt][1]));
            mx1 = fmaxf(mx1, fmaxf(s_acc[nt][2], s_acc[nt][3]));
        }
        mx0 = fmaxf(mx0, __shfl_xor_sync(0xffffffffu, mx0, 1));
        mx0 = fmaxf(mx0, __shfl_xor_sync(0xffffffffu, mx0, 2));
        mx1 = fmaxf(mx1, __shfl_xor_sync(0xffffffffu, mx1, 1));
        mx1 = fmaxf(mx1, __shfl_xor_sync(0xffffffffu, mx1, 2));

        const float mn0 = fmaxf(m0r, mx0);
        const float mn1 = fmaxf(m1r, mx1);
        const float cr0 = __expf(m0r - mn0);
        const float cr1 = __expf(m1r - mn1);
        l0 *= cr0; l1 *= cr1;
        #pragma unroll
        for (int dt = 0; dt < 8; dt++) {
            o_acc[dt][0] *= cr0; o_acc[dt][1] *= cr0;
            o_acc[dt][2] *= cr1; o_acc[dt][3] *= cr1;
        }

        float rs0 = 0.f, rs1 = 0.f;
        #pragma unroll
        for (int nt = 0; nt < 8; nt++) {
            const float p0 = __expf(s_acc[nt][0] - mn0);
            const float p1 = __expf(s_acc[nt][1] - mn0);
            const float p2 = __expf(s_acc[nt][2] - mn1);
            const float p3 = __expf(s_acc[nt][3] - mn1);
            rs0 += p0 + p1; rs1 += p2 + p3;
            const int c0 = nt * 8 + 2 * lk;
            Ps[m0 * QS_STRIDE + c0]           = f2tf(p0);
            Ps[m0 * QS_STRIDE + c0 + 1]       = f2tf(p1);
            Ps[(m0 + 8) * QS_STRIDE + c0]     = f2tf(p2);
            Ps[(m0 + 8) * QS_STRIDE + c0 + 1] = f2tf(p3);
        }
        rs0 += __shfl_xor_sync(0xffffffffu, rs0, 1);
        rs0 += __shfl_xor_sync(0xffffffffu, rs0, 2);
        rs1 += __shfl_xor_sync(0xffffffffu, rs1, 1);
        rs1 += __shfl_xor_sync(0xffffffffu, rs1, 2);
        l0 += rs0; l1 += rs1;
        m0r = mn0; m1r = mn1;

        __syncwarp();   // Ps (own-warp rows) visible before A-frag loads

        #pragma unroll
        for (int ks = 0; ks < 8; ks++) {
            const int kk = ks * 8;
            const uint32_t a0 = Ps[m0 * QS_STRIDE + kk + lk];
            const uint32_t a1 = Ps[(m0 + 8) * QS_STRIDE + kk + lk];
            const uint32_t a2 = Ps[m0 * QS_STRIDE + kk + 4 + lk];
            const uint32_t a3 = Ps[(m0 + 8) * QS_STRIDE + kk + 4 + lk];
            #pragma unroll
            for (int dt = 0; dt < 8; dt++) {
                const int n0 = dt * 8 + lq;
                const uint32_t b0 = Vb[(kk + lk) * VS_STRIDE + n0];
                const uint32_t b1 = Vb[(kk + 4 + lk) * VS_STRIDE + n0];
                mma_tf32(o_acc[dt], a0, a1, a2, a3, b0, b1);
            }
        }
        __syncwarp();   // PV reads done before next iter's Ps overwrite

        if (kb < qb) store_kv(buf ^ 1);   // other buffer; readers synced out
        __syncthreads();
    }

    const float inv0 = 1.f / l0;
    const float inv1 = 1.f / l1;
    float* Og = out + ((size_t)(b * T_ + qb * 64)) * DM + h * DK;
    #pragma unroll
    for (int dt = 0; dt < 8; dt++) {
        const int col = dt * 8 + 2 * lk;
        float2 v0 = make_float2(o_acc[dt][0] * inv0, o_acc[dt][1] * inv0);
        float2 v1 = make_float2(o_acc[dt][2] * inv1, o_acc[dt][3] * inv1);
        *(float2*)&Og[(size_t)m0 * DM + col]       = v0;
        *(float2*)&Og[(size_t)(m0 + 8) * DM + col] = v1;
    }
}

// ---------------------------------------------------------------------------
extern "C" void kernel_launch(void* const* d_in, const int* in_sizes, int n_in,
                              void* d_out, int out_size)
{
    const float* x   = (const float*)d_in[0];
    const int*   pos = (const int*)d_in[1];
    const float* Wq  = (const float*)d_in[2];
    const float* bq  = (const float*)d_in[3];
    const float* Wk  = (const float*)d_in[4];
    const float* bk  = (const float*)d_in[5];
    // d_in[6]=Wv, d_in[7]=bv unused (reference uses Wq/bq for V)
    const float* Wo  = (const float*)d_in[8];
    const float* bo  = (const float*)d_in[9];
    float* out = (float*)d_out;

    float *QV, *Qr, *Kr, *At;
    cudaGetSymbolAddress((void**)&QV, g_QV);
    cudaGetSymbolAddress((void**)&Qr, g_Qr);
    cudaGetSymbolAddress((void**)&Kr, g_Kr);
    cudaGetSymbolAddress((void**)&At, g_At);

    // Idempotent, called every time (no static guards per harness rules).
    cudaFuncSetAttribute(flash_attn_mma,
                         cudaFuncAttributeMaxDynamicSharedMemorySize,
                         FLASH_SMEM);

    // Fused Q+K projections with RoPE epilogue: grid (16, 32)
    gemm_qk<<<dim3(16, 32), 256>>>(QV, Qr, Kr, x, Wq, Wk, bq, bk, pos);

    flash_attn_mma<<<dim3(T_ / 64, NH, B_), 128, FLASH_SMEM>>>(At, Qr, Kr, QV);

    // Output projection: grid (8, 32)
    gemm_single<<<dim3(8, 32), 256>>>(out, At, Wo, bo);
}